// round 2
// baseline (speedup 1.0000x reference)
#include <cuda_runtime.h>
#include <cstdint>

#define B_  32
#define S_  2048
#define D_  64
// 1 / sqrt(512)  (D_MODEL = 512 in the reference, NOT head dim!)
#define SCALE_ 0.044194173824159216f

#define NEG_INF __int_as_float(0xff800000)

// ---------------- f32x2 helpers (FFMA2 via PTX, ptxas never emits from C++) ---
__device__ __forceinline__ unsigned long long fma2(unsigned long long a,
                                                   unsigned long long b,
                                                   unsigned long long c) {
    unsigned long long d;
    asm("fma.rn.f32x2 %0, %1, %2, %3;" : "=l"(d) : "l"(a), "l"(b), "l"(c));
    return d;
}
__device__ __forceinline__ unsigned long long bcast2(float x) {
    unsigned long long r;
    unsigned int u = __float_as_uint(x);
    asm("mov.b64 %0, {%1, %1};" : "=l"(r) : "r"(u));
    return r;
}
__device__ __forceinline__ float lo2(unsigned long long a) {
    return __uint_as_float((unsigned int)(a & 0xffffffffull));
}
__device__ __forceinline__ float hi2(unsigned long long a) {
    return __uint_as_float((unsigned int)(a >> 32));
}

// =============================================================================
// K1: masked logits = (Q*scale) @ K^T,  written raw into attn buffer
//   grid (S/128 ktiles, S/128 qtiles, B), 256 threads
//   smem: Qt[64][132], Kt[64][132]  (d-major, padded)  -> 67584 B dynamic
// =============================================================================
__global__ void qk_logits_kernel(const float* __restrict__ q,
                                 const float* __restrict__ k,
                                 const int* __restrict__ mask,
                                 float* __restrict__ attn) {
    extern __shared__ float sm1[];
    float* Qt = sm1;              // [64][132]
    float* Kt = sm1 + 64 * 132;   // [64][132]

    const int b  = blockIdx.z;
    const int q0 = blockIdx.y * 128;
    const int k0 = blockIdx.x * 128;
    const int tid = threadIdx.x;

    const float* qg = q + (size_t)b * S_ * D_;
    const float* kg = k + (size_t)b * S_ * D_;

    // stage (transpose to d-major), fold scale into Q
    #pragma unroll 4
    for (int idx = tid; idx < 128 * 64; idx += 256) {
        int row = idx >> 6;
        int d   = idx & 63;
        Qt[d * 132 + row] = qg[(size_t)(q0 + row) * D_ + d] * SCALE_;
        Kt[d * 132 + row] = kg[(size_t)(k0 + row) * D_ + d];
    }
    __syncthreads();

    const int ttx = tid & 15;   // k-col group
    const int tty = tid >> 4;   // q-row group

    unsigned long long acc[8][4];
    #pragma unroll
    for (int i = 0; i < 8; i++)
        #pragma unroll
        for (int n = 0; n < 4; n++) acc[i][n] = 0ull;

    #pragma unroll 8
    for (int d = 0; d < 64; ++d) {
        const float* qr = &Qt[d * 132 + tty * 8];
        float4 qa = *(const float4*)qr;
        float4 qb = *(const float4*)(qr + 4);
        const float* kr = &Kt[d * 132 + ttx * 8];
        ulonglong2 kA = *(const ulonglong2*)kr;        // (k0,k1),(k2,k3)
        ulonglong2 kB = *(const ulonglong2*)(kr + 4);  // (k4,k5),(k6,k7)
        float qs[8] = {qa.x, qa.y, qa.z, qa.w, qb.x, qb.y, qb.z, qb.w};
        #pragma unroll
        for (int i = 0; i < 8; i++) {
            unsigned long long qq = bcast2(qs[i]);
            acc[i][0] = fma2(qq, kA.x, acc[i][0]);
            acc[i][1] = fma2(qq, kA.y, acc[i][1]);
            acc[i][2] = fma2(qq, kB.x, acc[i][2]);
            acc[i][3] = fma2(qq, kB.y, acc[i][3]);
        }
    }

    // epilogue: mask (int32 bool) + store raw logits
    #pragma unroll
    for (int i = 0; i < 8; i++) {
        int qi = q0 + tty * 8 + i;
        const int* mrow =
            mask + ((size_t)b * S_ + qi) * S_ + k0 + ttx * 8;
        float* orow = attn + ((size_t)b * S_ + qi) * S_ + k0 + ttx * 8;
        int4 m0 = *(const int4*)mrow;
        int4 m1 = *(const int4*)(mrow + 4);
        int mm[8] = {m0.x, m0.y, m0.z, m0.w, m1.x, m1.y, m1.z, m1.w};
        float vals[8];
        #pragma unroll
        for (int n = 0; n < 4; n++) {
            vals[2 * n]     = lo2(acc[i][n]);
            vals[2 * n + 1] = hi2(acc[i][n]);
        }
        #pragma unroll
        for (int j = 0; j < 8; j++)
            if (mm[j]) vals[j] = NEG_INF;
        float4 w0 = {vals[0], vals[1], vals[2], vals[3]};
        float4 w1 = {vals[4], vals[5], vals[6], vals[7]};
        *(float4*)orow       = w0;
        *(float4*)(orow + 4) = w1;
    }
}

// =============================================================================
// K2: row-wise softmax in place. One block (256 thr) per row of 2048.
// =============================================================================
__global__ void softmax_rows_kernel(float* __restrict__ attn) {
    __shared__ float red[8];
    const size_t row = blockIdx.x;
    float* p = attn + row * (size_t)S_;
    const int t    = threadIdx.x;
    const int lane = t & 31;
    const int warp = t >> 5;

    float4 a0 = *(const float4*)(p + t * 8);
    float4 a1 = *(const float4*)(p + t * 8 + 4);
    float v[8] = {a0.x, a0.y, a0.z, a0.w, a1.x, a1.y, a1.z, a1.w};

    float m = v[0];
    #pragma unroll
    for (int i = 1; i < 8; i++) m = fmaxf(m, v[i]);
    #pragma unroll
    for (int off = 16; off; off >>= 1)
        m = fmaxf(m, __shfl_xor_sync(0xffffffffu, m, off));
    if (lane == 0) red[warp] = m;
    __syncthreads();
    m = red[0];
    #pragma unroll
    for (int i = 1; i < 8; i++) m = fmaxf(m, red[i]);
    __syncthreads();

    float s = 0.f;
    #pragma unroll
    for (int i = 0; i < 8; i++) {
        v[i] = __expf(v[i] - m);   // exp(-inf - m) -> 0
        s += v[i];
    }
    #pragma unroll
    for (int off = 16; off; off >>= 1)
        s += __shfl_xor_sync(0xffffffffu, s, off);
    if (lane == 0) red[warp] = s;
    __syncthreads();
    s = 0.f;
    #pragma unroll
    for (int i = 0; i < 8; i++) s += red[i];

    float inv = 1.0f / s;
    float4 w0 = {v[0] * inv, v[1] * inv, v[2] * inv, v[3] * inv};
    float4 w1 = {v[4] * inv, v[5] * inv, v[6] * inv, v[7] * inv};
    *(float4*)(p + t * 8)     = w0;
    *(float4*)(p + t * 8 + 4) = w1;
}

// =============================================================================
// K3: out = attn @ V.  grid (S/128, B), 256 threads.
//   smem: At[64][132] (j-major over i), Vs[64][68]   -> 51200 B dynamic
//   per thread: 8 i-rows x 4 d-cols, d-pair packed f32x2
// =============================================================================
__global__ void pv_kernel(const float* __restrict__ attn,
                          const float* __restrict__ v,
                          float* __restrict__ out) {
    extern __shared__ float sm3[];
    float* At = sm3;              // [64][132]  At[j][i]
    float* Vs = sm3 + 64 * 132;   // [64][68]   Vs[j][d]

    const int b  = blockIdx.y;
    const int i0 = blockIdx.x * 128;
    const int tid = threadIdx.x;
    const int ttx = tid & 15;   // d group: d0 = ttx*4
    const int tty = tid >> 4;   // i group: i0_loc = tty*8

    const float* ab = attn + (size_t)b * S_ * S_;
    const float* vb = v + (size_t)b * S_ * D_;

    unsigned long long acc[8][2];
    #pragma unroll
    for (int i = 0; i < 8; i++) { acc[i][0] = 0ull; acc[i][1] = 0ull; }

    for (int jc = 0; jc < S_ / 64; ++jc) {
        const int j0 = jc * 64;
        #pragma unroll 4
        for (int idx = tid; idx < 128 * 64; idx += 256) {
            int i = idx >> 6;
            int j = idx & 63;
            At[j * 132 + i] = ab[(size_t)(i0 + i) * S_ + j0 + j];
        }
        #pragma unroll 2
        for (int idx = tid; idx < 64 * 64; idx += 256) {
            int j = idx >> 6;
            int d = idx & 63;
            Vs[j * 68 + d] = vb[(size_t)(j0 + j) * D_ + d];
        }
        __syncthreads();

        #pragma unroll 8
        for (int j = 0; j < 64; ++j) {
            const float* ar = &At[j * 132 + tty * 8];
            float4 aa = *(const float4*)ar;
            float4 ab2 = *(const float4*)(ar + 4);
            ulonglong2 vv = *(const ulonglong2*)(&Vs[j * 68 + ttx * 4]);
            float as[8] = {aa.x, aa.y, aa.z, aa.w, ab2.x, ab2.y, ab2.z, ab2.w};
            #pragma unroll
            for (int i = 0; i < 8; i++) {
                unsigned long long aq = bcast2(as[i]);
                acc[i][0] = fma2(aq, vv.x, acc[i][0]);
                acc[i][1] = fma2(aq, vv.y, acc[i][1]);
            }
        }
        __syncthreads();
    }

    #pragma unroll
    for (int i = 0; i < 8; i++) {
        float4 w = {lo2(acc[i][0]), hi2(acc[i][0]),
                    lo2(acc[i][1]), hi2(acc[i][1])};
        *(float4*)(out + ((size_t)b * S_ + i0 + tty * 8 + i) * D_ + ttx * 4) = w;
    }
}

// =============================================================================
extern "C" void kernel_launch(void* const* d_in, const int* in_sizes, int n_in,
                              void* d_out, int out_size) {
    const float* q = (const float*)d_in[0];
    const float* k = (const float*)d_in[1];
    const float* v = (const float*)d_in[2];
    const int* mask = (const int*)d_in[3];

    float* out  = (float*)d_out;                      // [B,S,D]
    float* attn = out + (size_t)B_ * S_ * D_;         // [B,S,S]

    const int SMEM1 = 2 * 64 * 132 * 4;   // 67584
    const int SMEM3 = (64 * 132 + 64 * 68) * 4;  // 51200

    cudaFuncSetAttribute(qk_logits_kernel,
                         cudaFuncAttributeMaxDynamicSharedMemorySize, SMEM1);
    cudaFuncSetAttribute(pv_kernel,
                         cudaFuncAttributeMaxDynamicSharedMemorySize, SMEM3);

    dim3 g1(S_ / 128, S_ / 128, B_);
    qk_logits_kernel<<<g1, 256, SMEM1>>>(q, k, mask, attn);

    softmax_rows_kernel<<<B_ * S_, 256>>>(attn);

    dim3 g3(S_ / 128, B_);
    pv_kernel<<<g3, 256, SMEM3>>>(attn, v, out);
}

// round 4
// speedup vs baseline: 1.0126x; 1.0126x over previous
#include <cuda_runtime.h>
#include <cstdint>

#define B_ 32
#define S_ 2048
#define D_ 64
// 1/sqrt(512): D_MODEL=512 in reference, NOT head dim
#define SCALE_ 0.044194173824159216f

#define QS_STRIDE 68   // padded fp32 stride for 64-wide K-major tiles
#define P_STRIDE  132  // padded fp32 stride for 128-wide P tile

__device__ __forceinline__ uint32_t f2tf32(float x) {
    uint32_t r;
    asm("cvt.rna.tf32.f32 %0, %1;" : "=r"(r) : "f"(x));
    return r;
}

__device__ __forceinline__ void mma8(float (&d)[4], const uint32_t (&a)[4],
                                     const uint32_t (&b)[2]) {
    asm volatile(
        "mma.sync.aligned.m16n8k8.row.col.f32.tf32.tf32.f32 "
        "{%0,%1,%2,%3}, {%4,%5,%6,%7}, {%8,%9}, {%0,%1,%2,%3};"
        : "+f"(d[0]), "+f"(d[1]), "+f"(d[2]), "+f"(d[3])
        : "r"(a[0]), "r"(a[1]), "r"(a[2]), "r"(a[3]), "r"(b[0]), "r"(b[1]));
}

// =============================================================================
// Fused attention: one block owns 128 q-rows x full S.
//   grid (16, 32), 256 threads (8 warps: 4 m-warps x 2 n-warps)
//   smem: rs[128] | Qs 128x68 | Ks 128x68 | Vs 128x68 | P 128x132 (tf32 bits)
// =============================================================================
__global__ __launch_bounds__(256) void fused_attn_kernel(
        const float* __restrict__ q, const float* __restrict__ k,
        const float* __restrict__ v, const int* __restrict__ mask,
        float* __restrict__ attn, float* __restrict__ out) {
    extern __shared__ char sm[];
    float*    rs = (float*)sm;                      // [128] rowsums -> inv
    uint32_t* Qs = (uint32_t*)(sm + 512);           // 128x68
    uint32_t* Ks = (uint32_t*)(sm + 35328);         // 128x68
    uint32_t* Vs = (uint32_t*)(sm + 70144);         // 128x68
    uint32_t* P  = (uint32_t*)(sm + 104960);        // 128x132

    const int tid = threadIdx.x, lane = tid & 31, wid = tid >> 5;
    const int wm = (wid & 3) * 32;   // warp m-base (rows)
    const int wn = (wid >> 2);       // warp n-half (0/1)
    const int b  = blockIdx.y, i0 = blockIdx.x * 128;
    const int g  = lane >> 2, e = lane & 3;

    if (tid < 128) rs[tid] = 0.f;

    // ---- stage Q once (scale folded, tf32) ----
    const float* qg = q + ((size_t)b * S_ + i0) * D_;
    #pragma unroll
    for (int idx = tid; idx < 2048; idx += 256) {
        int row = idx >> 4, c4 = (idx & 15) << 2;
        float4 t = *(const float4*)(qg + row * D_ + c4);
        uint4 u = { f2tf32(t.x * SCALE_), f2tf32(t.y * SCALE_),
                    f2tf32(t.z * SCALE_), f2tf32(t.w * SCALE_) };
        *(uint4*)(Qs + row * QS_STRIDE + c4) = u;
    }

    float accpv[2][4][4];
    #pragma unroll
    for (int mi = 0; mi < 2; mi++)
        #pragma unroll
        for (int nj = 0; nj < 4; nj++)
            #pragma unroll
            for (int c = 0; c < 4; c++) accpv[mi][nj][c] = 0.f;

    #pragma unroll 1
    for (int ct = 0; ct < 16; ++ct) {
        const int j0 = ct * 128;
        // ---- stage K, V tiles (tf32) ----
        const float* kg = k + ((size_t)b * S_ + j0) * D_;
        const float* vg = v + ((size_t)b * S_ + j0) * D_;
        #pragma unroll
        for (int idx = tid; idx < 2048; idx += 256) {
            int row = idx >> 4, c4 = (idx & 15) << 2;
            float4 t = *(const float4*)(kg + row * D_ + c4);
            uint4 u = { f2tf32(t.x), f2tf32(t.y), f2tf32(t.z), f2tf32(t.w) };
            *(uint4*)(Ks + row * QS_STRIDE + c4) = u;
            float4 t2 = *(const float4*)(vg + row * D_ + c4);
            uint4 u2 = { f2tf32(t2.x), f2tf32(t2.y), f2tf32(t2.z), f2tf32(t2.w) };
            *(uint4*)(Vs + row * QS_STRIDE + c4) = u2;
        }
        __syncthreads();

        // ---- QK^T: warp tile 32x64, m16n8k8 tf32 ----
        float accq[2][8][4];
        #pragma unroll
        for (int mi = 0; mi < 2; mi++)
            #pragma unroll
            for (int nj = 0; nj < 8; nj++)
                #pragma unroll
                for (int c = 0; c < 4; c++) accq[mi][nj][c] = 0.f;

        #pragma unroll
        for (int ks = 0; ks < 8; ++ks) {
            uint32_t af[2][4];
            #pragma unroll
            for (int mi = 0; mi < 2; mi++) {
                int r0 = wm + mi * 16 + g;
                af[mi][0] = Qs[r0 * QS_STRIDE + ks * 8 + e];
                af[mi][1] = Qs[(r0 + 8) * QS_STRIDE + ks * 8 + e];
                af[mi][2] = Qs[r0 * QS_STRIDE + ks * 8 + 4 + e];
                af[mi][3] = Qs[(r0 + 8) * QS_STRIDE + ks * 8 + 4 + e];
            }
            #pragma unroll
            for (int nj = 0; nj < 8; nj++) {
                int col = wn * 64 + nj * 8 + g;
                uint32_t bf[2];
                bf[0] = Ks[col * QS_STRIDE + ks * 8 + e];
                bf[1] = Ks[col * QS_STRIDE + ks * 8 + 4 + e];
                mma8(accq[0][nj], af[0], bf);
                mma8(accq[1][nj], af[1], bf);
            }
        }

        // ---- epilogue: mask -> exp -> gmem raw store + smem P (tf32) ----
        #pragma unroll
        for (int mi = 0; mi < 2; mi++) {
            #pragma unroll
            for (int h = 0; h < 2; h++) {
                int rl = wm + mi * 16 + h * 8 + g;
                size_t gro = ((size_t)b * S_ + i0 + rl) * S_ + j0 + wn * 64;
                const int* mrow = mask + gro;
                float* arow = attn + gro;
                #pragma unroll
                for (int nj = 0; nj < 8; nj++) {
                    int ci = nj * 8 + 2 * e;
                    int2 m = *(const int2*)(mrow + ci);
                    float e0 = m.x ? 0.f : __expf(accq[mi][nj][h * 2 + 0]);
                    float e1 = m.y ? 0.f : __expf(accq[mi][nj][h * 2 + 1]);
                    float2 w = { e0, e1 };
                    *(float2*)(arow + ci) = w;
                    uint2 pw = { f2tf32(e0), f2tf32(e1) };
                    *(uint2*)(P + rl * P_STRIDE + wn * 64 + ci) = pw;
                }
            }
        }
        __syncthreads();

        // ---- rowsum from P (tf32 values; error ~1e-5 in the sum) ----
        {
            int row = tid >> 1, base = (tid & 1) * 64;
            const float* pr = (const float*)(P + row * P_STRIDE + base);
            float s = 0.f;
            #pragma unroll
            for (int i = 0; i < 16; ++i) {
                float4 t = *(const float4*)(pr + i * 4);
                s += (t.x + t.y) + (t.z + t.w);
            }
            s += __shfl_xor_sync(0xffffffffu, s, 1);
            if (!(tid & 1)) rs[row] += s;
        }

        // ---- PV: out_acc += P @ V, warp tile 32x32 ----
        #pragma unroll
        for (int ks = 0; ks < 16; ++ks) {
            uint32_t af[2][4];
            #pragma unroll
            for (int mi = 0; mi < 2; mi++) {
                int r0 = wm + mi * 16 + g;
                af[mi][0] = P[r0 * P_STRIDE + ks * 8 + e];
                af[mi][1] = P[(r0 + 8) * P_STRIDE + ks * 8 + e];
                af[mi][2] = P[r0 * P_STRIDE + ks * 8 + 4 + e];
                af[mi][3] = P[(r0 + 8) * P_STRIDE + ks * 8 + 4 + e];
            }
            #pragma unroll
            for (int nj = 0; nj < 4; nj++) {
                int d0 = wn * 32 + nj * 8 + g;
                uint32_t bf[2];
                bf[0] = Vs[(ks * 8 + e) * QS_STRIDE + d0];
                bf[1] = Vs[(ks * 8 + 4 + e) * QS_STRIDE + d0];
                mma8(accpv[0][nj], af[0], bf);
                mma8(accpv[1][nj], af[1], bf);
            }
        }
        __syncthreads();
    }

    // ---- inverse rowsums ----
    if (tid < 128) rs[tid] = __frcp_rn(rs[tid]);
    __syncthreads();

    // ---- out = acc_pv * inv ----
    #pragma unroll
    for (int mi = 0; mi < 2; mi++) {
        #pragma unroll
        for (int h = 0; h < 2; h++) {
            int rl = wm + mi * 16 + h * 8 + g;
            float sc = rs[rl];
            float* orow = out + ((size_t)b * S_ + i0 + rl) * D_ + wn * 32;
            #pragma unroll
            for (int nj = 0; nj < 4; nj++) {
                int ci = nj * 8 + 2 * e;
                float2 w = { accpv[mi][nj][h * 2 + 0] * sc,
                             accpv[mi][nj][h * 2 + 1] * sc };
                *(float2*)(orow + ci) = w;
            }
        }
    }

    // ---- pass 2: normalize this block's attn stripe in place ----
    float* ab = attn + ((size_t)b * S_ + i0) * S_;
    for (int idx = tid; idx < 128 * 512; idx += 256) {
        int row = idx >> 9, c4 = (idx & 511) << 2;
        float sc = rs[row];
        float4* p = (float4*)(ab + (size_t)row * S_ + c4);
        float4 t = *p;
        t.x *= sc; t.y *= sc; t.z *= sc; t.w *= sc;
        *p = t;
    }
}

// =============================================================================
extern "C" void kernel_launch(void* const* d_in, const int* in_sizes, int n_in,
                              void* d_out, int out_size) {
    const float* q = (const float*)d_in[0];
    const float* k = (const float*)d_in[1];
    const float* v = (const float*)d_in[2];
    const int* mask = (const int*)d_in[3];

    float* out  = (float*)d_out;                  // [B,S,D]
    float* attn = out + (size_t)B_ * S_ * D_;     // [B,S,S]

    const int SMEM = 104960 + 128 * P_STRIDE * 4;  // 172544
    cudaFuncSetAttribute(fused_attn_kernel,
                         cudaFuncAttributeMaxDynamicSharedMemorySize, SMEM);

    dim3 grid(S_ / 128, B_);
    fused_attn_kernel<<<grid, 256, SMEM>>>(q, k, v, mask, attn, out);
}

// round 5
// speedup vs baseline: 1.3158x; 1.2994x over previous
#include <cuda_runtime.h>
#include <cstdint>

#define B_ 32
#define S_ 2048
#define D_ 64
// 1/sqrt(512): D_MODEL=512 in reference, NOT head dim
#define SCALE_ 0.044194173824159216f

#define ST 68  // padded word stride for 64-wide smem tiles

__device__ __forceinline__ uint32_t f2tf32(float x) {
    uint32_t r;
    asm("cvt.rna.tf32.f32 %0, %1;" : "=r"(r) : "f"(x));
    return r;
}

__device__ __forceinline__ void mma8(float (&d)[4], const uint32_t (&a)[4],
                                     const uint32_t (&b)[2]) {
    asm volatile(
        "mma.sync.aligned.m16n8k8.row.col.f32.tf32.tf32.f32 "
        "{%0,%1,%2,%3}, {%4,%5,%6,%7}, {%8,%9}, {%0,%1,%2,%3};"
        : "+f"(d[0]), "+f"(d[1]), "+f"(d[2]), "+f"(d[3])
        : "r"(a[0]), "r"(a[1]), "r"(a[2]), "r"(a[3]), "r"(b[0]), "r"(b[1]));
}

// =============================================================================
// Fused attention: block = 128 q-rows x full S, k-tiles of 64.
//   grid (16, 32), 256 threads (8 warps: 4 m x 2 n), 2 CTAs/SM.
//   smem (102.5KB): rs[128] | Qs 128x68 | Ks 64x68 | Vs 64x68 | P 128x68
// =============================================================================
__global__ __launch_bounds__(256, 2) void fused_attn_kernel(
        const float* __restrict__ q, const float* __restrict__ k,
        const float* __restrict__ v, const int* __restrict__ mask,
        float* __restrict__ attn, float* __restrict__ out) {
    extern __shared__ char sm[];
    float*    rs = (float*)sm;                   // [128]
    uint32_t* Qs = (uint32_t*)(sm + 512);        // 128x68
    uint32_t* Ks = (uint32_t*)(sm + 35328);      // 64x68
    uint32_t* Vs = (uint32_t*)(sm + 52736);      // 64x68  (Vs[j][d])
    uint32_t* P  = (uint32_t*)(sm + 70144);      // 128x68

    const int tid = threadIdx.x, lane = tid & 31, wid = tid >> 5;
    const int wm = (wid & 3) * 32;   // warp m-base
    const int wn = wid >> 2;         // warp n-half (0/1)
    const int g = lane >> 2, e = lane & 3;
    const int b = blockIdx.y, i0 = blockIdx.x * 128;

    if (tid < 128) rs[tid] = 0.f;

    // ---- stage Q once (scale folded, tf32) ----
    const float* qg = q + ((size_t)b * S_ + i0) * D_;
    #pragma unroll
    for (int idx = tid; idx < 2048; idx += 256) {
        int row = idx >> 4, c4 = (idx & 15) << 2;
        float4 t = *(const float4*)(qg + row * D_ + c4);
        uint4 u = { f2tf32(t.x * SCALE_), f2tf32(t.y * SCALE_),
                    f2tf32(t.z * SCALE_), f2tf32(t.w * SCALE_) };
        *(uint4*)(Qs + row * ST + c4) = u;
    }

    float accpv[2][4][4];
    #pragma unroll
    for (int mi = 0; mi < 2; mi++)
        #pragma unroll
        for (int nj = 0; nj < 4; nj++)
            #pragma unroll
            for (int c = 0; c < 4; c++) accpv[mi][nj][c] = 0.f;

    #pragma unroll 1
    for (int ct = 0; ct < 32; ++ct) {
        const int j0 = ct * 64;
        // ---- stage K, V (64x64 each, tf32) ----
        const float* kg = k + ((size_t)b * S_ + j0) * D_;
        const float* vg = v + ((size_t)b * S_ + j0) * D_;
        #pragma unroll
        for (int idx = tid; idx < 1024; idx += 256) {
            int row = idx >> 4, c4 = (idx & 15) << 2;
            float4 t = *(const float4*)(kg + row * D_ + c4);
            uint4 u = { f2tf32(t.x), f2tf32(t.y), f2tf32(t.z), f2tf32(t.w) };
            *(uint4*)(Ks + row * ST + c4) = u;
            float4 t2 = *(const float4*)(vg + row * D_ + c4);
            uint4 u2 = { f2tf32(t2.x), f2tf32(t2.y), f2tf32(t2.z), f2tf32(t2.w) };
            *(uint4*)(Vs + row * ST + c4) = u2;
        }
        __syncthreads();

        // ---- QK^T: warp tile 32x32 ----
        float accq[2][4][4];
        #pragma unroll
        for (int mi = 0; mi < 2; mi++)
            #pragma unroll
            for (int nj = 0; nj < 4; nj++)
                #pragma unroll
                for (int c = 0; c < 4; c++) accq[mi][nj][c] = 0.f;

        #pragma unroll
        for (int ks = 0; ks < 8; ++ks) {
            uint32_t af[2][4];
            #pragma unroll
            for (int mi = 0; mi < 2; mi++) {
                int r0 = wm + mi * 16 + g;
                af[mi][0] = Qs[r0 * ST + ks * 8 + e];
                af[mi][1] = Qs[(r0 + 8) * ST + ks * 8 + e];
                af[mi][2] = Qs[r0 * ST + ks * 8 + 4 + e];
                af[mi][3] = Qs[(r0 + 8) * ST + ks * 8 + 4 + e];
            }
            #pragma unroll
            for (int nj = 0; nj < 4; nj++) {
                int col = wn * 32 + nj * 8 + g;
                uint32_t bf[2];
                bf[0] = Ks[col * ST + ks * 8 + e];
                bf[1] = Ks[col * ST + ks * 8 + 4 + e];
                mma8(accq[0][nj], af[0], bf);
                mma8(accq[1][nj], af[1], bf);
            }
        }

        // ---- dump raw logits to P ----
        #pragma unroll
        for (int mi = 0; mi < 2; mi++)
            #pragma unroll
            for (int h = 0; h < 2; h++) {
                int rl = wm + mi * 16 + h * 8 + g;
                #pragma unroll
                for (int nj = 0; nj < 4; nj++) {
                    uint2 w = { __float_as_uint(accq[mi][nj][h * 2 + 0]),
                                __float_as_uint(accq[mi][nj][h * 2 + 1]) };
                    *(uint2*)(P + rl * ST + wn * 32 + nj * 8 + 2 * e) = w;
                }
            }
        __syncthreads();

        // ---- P-pass: mask -> exp -> attn store + tf32 P + rowsum ----
        #pragma unroll
        for (int r2 = 0; r2 < 2; r2++) {
            int row = r2 * 64 + (tid >> 2);
            int cb  = (tid & 3) * 16;
            size_t gro = ((size_t)b * S_ + i0 + row) * S_ + j0 + cb;
            const int4* mrow = (const int4*)(mask + gro);
            float4* arow = (float4*)(attn + gro);
            float* pr = (float*)(P + row * ST + cb);
            float s = 0.f;
            #pragma unroll
            for (int i = 0; i < 4; i++) {
                int4 m = mrow[i];
                float4 t = *(const float4*)(pr + i * 4);
                float4 pv;
                pv.x = m.x ? 0.f : __expf(t.x);
                pv.y = m.y ? 0.f : __expf(t.y);
                pv.z = m.z ? 0.f : __expf(t.z);
                pv.w = m.w ? 0.f : __expf(t.w);
                s += (pv.x + pv.y) + (pv.z + pv.w);
                arow[i] = pv;
                uint4 u = { f2tf32(pv.x), f2tf32(pv.y), f2tf32(pv.z), f2tf32(pv.w) };
                *(uint4*)(pr + i * 4) = u;
            }
            s += __shfl_xor_sync(0xffffffffu, s, 1);
            s += __shfl_xor_sync(0xffffffffu, s, 2);
            if ((tid & 3) == 0) rs[row] += s;
        }
        __syncthreads();

        // ---- PV: accpv += P @ V ----
        #pragma unroll
        for (int ks = 0; ks < 8; ++ks) {
            uint32_t af[2][4];
            #pragma unroll
            for (int mi = 0; mi < 2; mi++) {
                int r0 = wm + mi * 16 + g;
                af[mi][0] = P[r0 * ST + ks * 8 + e];
                af[mi][1] = P[(r0 + 8) * ST + ks * 8 + e];
                af[mi][2] = P[r0 * ST + ks * 8 + 4 + e];
                af[mi][3] = P[(r0 + 8) * ST + ks * 8 + 4 + e];
            }
            #pragma unroll
            for (int nj = 0; nj < 4; nj++) {
                int d0 = wn * 32 + nj * 8 + g;
                uint32_t bf[2];
                bf[0] = Vs[(ks * 8 + e) * ST + d0];
                bf[1] = Vs[(ks * 8 + 4 + e) * ST + d0];
                mma8(accpv[0][nj], af[0], bf);
                mma8(accpv[1][nj], af[1], bf);
            }
        }
        __syncthreads();
    }

    // ---- inverse rowsums ----
    if (tid < 128) rs[tid] = __frcp_rn(rs[tid]);
    __syncthreads();

    // ---- out = accpv * inv ----
    #pragma unroll
    for (int mi = 0; mi < 2; mi++)
        #pragma unroll
        for (int h = 0; h < 2; h++) {
            int rl = wm + mi * 16 + h * 8 + g;
            float sc = rs[rl];
            float* orow = out + ((size_t)b * S_ + i0 + rl) * D_ + wn * 32;
            #pragma unroll
            for (int nj = 0; nj < 4; nj++) {
                float2 w = { accpv[mi][nj][h * 2 + 0] * sc,
                             accpv[mi][nj][h * 2 + 1] * sc };
                *(float2*)(orow + nj * 8 + 2 * e) = w;
            }
        }

    // ---- pass 2: normalize attn stripe in place ----
    float* ab = attn + ((size_t)b * S_ + i0) * S_;
    #pragma unroll 4
    for (int idx = tid; idx < 128 * 512; idx += 256) {
        int row = idx >> 9, c4 = (idx & 511) << 2;
        float sc = rs[row];
        float4* p = (float4*)(ab + (size_t)row * S_ + c4);
        float4 t = *p;
        t.x *= sc; t.y *= sc; t.z *= sc; t.w *= sc;
        *p = t;
    }
}

// =============================================================================
extern "C" void kernel_launch(void* const* d_in, const int* in_sizes, int n_in,
                              void* d_out, int out_size) {
    const float* q = (const float*)d_in[0];
    const float* k = (const float*)d_in[1];
    const float* v = (const float*)d_in[2];
    const int* mask = (const int*)d_in[3];

    float* out  = (float*)d_out;                 // [B,S,D]
    float* attn = out + (size_t)B_ * S_ * D_;    // [B,S,S]

    const int SMEM = 104960;  // 102.5 KB -> 2 CTAs/SM
    cudaFuncSetAttribute(fused_attn_kernel,
                         cudaFuncAttributeMaxDynamicSharedMemorySize, SMEM);

    dim3 grid(S_ / 128, B_);
    fused_attn_kernel<<<grid, 256, SMEM>>>(q, k, v, mask, attn, out);
}

// round 6
// speedup vs baseline: 1.4021x; 1.0656x over previous
#include <cuda_runtime.h>
#include <cstdint>

#define B_ 32
#define S_ 2048
#define D_ 64
// (1/sqrt(512)) * log2(e): exp(logit) == exp2(mma_result)
#define SCALE2_ (0.044194173824159216f * 1.4426950408889634f)

#define ST 68  // padded word stride for 64-wide smem tiles

__device__ __forceinline__ uint32_t f2tf32(float x) {
    uint32_t r;
    asm("cvt.rna.tf32.f32 %0, %1;" : "=r"(r) : "f"(x));
    return r;
}

// masked exp2: m!=0 -> 0, else ex2(x). Predicated so masked lanes skip MUFU.
__device__ __forceinline__ float pexp2(int m, float x) {
    float r;
    asm("{\n\t.reg .pred p;\n\t"
        "setp.eq.s32 p, %1, 0;\n\t"
        "mov.f32 %0, 0f00000000;\n\t"
        "@p ex2.approx.f32 %0, %2;\n\t}"
        : "=f"(r) : "r"(m), "f"(x));
    return r;
}

__device__ __forceinline__ void mma8(float (&d)[4], const uint32_t (&a)[4],
                                     const uint32_t (&b)[2]) {
    asm volatile(
        "mma.sync.aligned.m16n8k8.row.col.f32.tf32.tf32.f32 "
        "{%0,%1,%2,%3}, {%4,%5,%6,%7}, {%8,%9}, {%0,%1,%2,%3};"
        : "+f"(d[0]), "+f"(d[1]), "+f"(d[2]), "+f"(d[3])
        : "r"(a[0]), "r"(a[1]), "r"(a[2]), "r"(a[3]), "r"(b[0]), "r"(b[1]));
}

// =============================================================================
// Fused attention: block = 64 q-rows x full S, k-tiles of 64.
//   grid (32, 32), 128 threads (4 warps: 2 m x 2 n), 4 CTAs/SM.
//   smem 52.5KB: rs[64] | Qs 64x68 | Ks 64x68 (aliased by P after QK) | Vs 64x68
// =============================================================================
__global__ __launch_bounds__(128, 4) void fused_attn_kernel(
        const float* __restrict__ q, const float* __restrict__ k,
        const float* __restrict__ v, const int* __restrict__ mask,
        float* __restrict__ attn, float* __restrict__ out) {
    extern __shared__ char sm[];
    float*    rs = (float*)sm;                   // [64]
    uint32_t* Qs = (uint32_t*)(sm + 256);        // 64x68
    uint32_t* Ks = (uint32_t*)(sm + 17664);      // 64x68 (P aliases this)
    uint32_t* Vs = (uint32_t*)(sm + 35072);      // 64x68 (Vs[j][d])
    uint32_t* P  = Ks;

    const int tid = threadIdx.x, lane = tid & 31, wid = tid >> 5;
    const int wm = (wid & 1) * 32;   // warp m-base
    const int wn = wid >> 1;         // warp n-half (0/1)
    const int g = lane >> 2, e = lane & 3;
    const int b = blockIdx.y, i0 = blockIdx.x * 64;

    if (tid < 64) rs[tid] = 0.f;

    // ---- stage Q once (scale*log2e folded, tf32) ----
    const float* qg = q + ((size_t)b * S_ + i0) * D_;
    #pragma unroll
    for (int idx = tid; idx < 1024; idx += 128) {
        int row = idx >> 4, c4 = (idx & 15) << 2;
        float4 t = *(const float4*)(qg + row * D_ + c4);
        uint4 u = { f2tf32(t.x * SCALE2_), f2tf32(t.y * SCALE2_),
                    f2tf32(t.z * SCALE2_), f2tf32(t.w * SCALE2_) };
        *(uint4*)(Qs + row * ST + c4) = u;
    }

    float accpv[2][4][4];
    #pragma unroll
    for (int mi = 0; mi < 2; mi++)
        #pragma unroll
        for (int nj = 0; nj < 4; nj++)
            #pragma unroll
            for (int c = 0; c < 4; c++) accpv[mi][nj][c] = 0.f;

    #pragma unroll 1
    for (int ct = 0; ct < 32; ++ct) {
        const int j0 = ct * 64;
        // ---- stage K, V (64x64 each, tf32) ----
        const float* kg = k + ((size_t)b * S_ + j0) * D_;
        const float* vg = v + ((size_t)b * S_ + j0) * D_;
        #pragma unroll
        for (int idx = tid; idx < 1024; idx += 128) {
            int row = idx >> 4, c4 = (idx & 15) << 2;
            float4 t = *(const float4*)(kg + row * D_ + c4);
            uint4 u = { f2tf32(t.x), f2tf32(t.y), f2tf32(t.z), f2tf32(t.w) };
            *(uint4*)(Ks + row * ST + c4) = u;
            float4 t2 = *(const float4*)(vg + row * D_ + c4);
            uint4 u2 = { f2tf32(t2.x), f2tf32(t2.y), f2tf32(t2.z), f2tf32(t2.w) };
            *(uint4*)(Vs + row * ST + c4) = u2;
        }
        __syncthreads();

        // ---- QK^T: warp tile 32x32 (result = log2e * logit) ----
        float accq[2][4][4];
        #pragma unroll
        for (int mi = 0; mi < 2; mi++)
            #pragma unroll
            for (int nj = 0; nj < 4; nj++)
                #pragma unroll
                for (int c = 0; c < 4; c++) accq[mi][nj][c] = 0.f;

        #pragma unroll
        for (int ks = 0; ks < 8; ++ks) {
            uint32_t af[2][4];
            #pragma unroll
            for (int mi = 0; mi < 2; mi++) {
                int r0 = wm + mi * 16 + g;
                af[mi][0] = Qs[r0 * ST + ks * 8 + e];
                af[mi][1] = Qs[(r0 + 8) * ST + ks * 8 + e];
                af[mi][2] = Qs[r0 * ST + ks * 8 + 4 + e];
                af[mi][3] = Qs[(r0 + 8) * ST + ks * 8 + 4 + e];
            }
            #pragma unroll
            for (int nj = 0; nj < 4; nj++) {
                int col = wn * 32 + nj * 8 + g;
                uint32_t bf[2];
                bf[0] = Ks[col * ST + ks * 8 + e];
                bf[1] = Ks[col * ST + ks * 8 + 4 + e];
                mma8(accq[0][nj], af[0], bf);
                mma8(accq[1][nj], af[1], bf);
            }
        }
        __syncthreads();   // all warps done reading Ks before P overwrites it

        // ---- dump raw log2-logits to P (aliases Ks) ----
        #pragma unroll
        for (int mi = 0; mi < 2; mi++)
            #pragma unroll
            for (int h = 0; h < 2; h++) {
                int rl = wm + mi * 16 + h * 8 + g;
                #pragma unroll
                for (int nj = 0; nj < 4; nj++) {
                    uint2 w = { __float_as_uint(accq[mi][nj][h * 2 + 0]),
                                __float_as_uint(accq[mi][nj][h * 2 + 1]) };
                    *(uint2*)(P + rl * ST + wn * 32 + nj * 8 + 2 * e) = w;
                }
            }
        __syncthreads();

        // ---- P-pass: mask -> predicated exp2 -> attn store + P + rowsum ----
        #pragma unroll
        for (int r2 = 0; r2 < 2; r2++) {
            int row = r2 * 32 + (tid >> 2);
            int cb  = (tid & 3) * 16;
            size_t gro = ((size_t)b * S_ + i0 + row) * S_ + j0 + cb;
            const int4* mrow = (const int4*)(mask + gro);
            float4* arow = (float4*)(attn + gro);
            float* pr = (float*)(P + row * ST + cb);
            float s = 0.f;
            #pragma unroll
            for (int i = 0; i < 4; i++) {
                int4 m = mrow[i];
                float4 t = *(const float4*)(pr + i * 4);
                float4 pv;
                pv.x = pexp2(m.x, t.x);
                pv.y = pexp2(m.y, t.y);
                pv.z = pexp2(m.z, t.z);
                pv.w = pexp2(m.w, t.w);
                s += (pv.x + pv.y) + (pv.z + pv.w);
                arow[i] = pv;
                *(float4*)(pr + i * 4) = pv;   // raw fp32; HMMA truncates to tf32
            }
            s += __shfl_xor_sync(0xffffffffu, s, 1);
            s += __shfl_xor_sync(0xffffffffu, s, 2);
            if ((tid & 3) == 0) rs[row] += s;
        }
        __syncthreads();

        // ---- PV: accpv += P @ V ----
        #pragma unroll
        for (int ks = 0; ks < 8; ++ks) {
            uint32_t af[2][4];
            #pragma unroll
            for (int mi = 0; mi < 2; mi++) {
                int r0 = wm + mi * 16 + g;
                af[mi][0] = P[r0 * ST + ks * 8 + e];
                af[mi][1] = P[(r0 + 8) * ST + ks * 8 + e];
                af[mi][2] = P[r0 * ST + ks * 8 + 4 + e];
                af[mi][3] = P[(r0 + 8) * ST + ks * 8 + 4 + e];
            }
            #pragma unroll
            for (int nj = 0; nj < 4; nj++) {
                int d0 = wn * 32 + nj * 8 + g;
                uint32_t bf[2];
                bf[0] = Vs[(ks * 8 + e) * ST + d0];
                bf[1] = Vs[(ks * 8 + 4 + e) * ST + d0];
                mma8(accpv[0][nj], af[0], bf);
                mma8(accpv[1][nj], af[1], bf);
            }
        }
        __syncthreads();
    }

    // ---- inverse rowsums ----
    if (tid < 64) rs[tid] = __frcp_rn(rs[tid]);
    __syncthreads();

    // ---- out = accpv * inv ----
    #pragma unroll
    for (int mi = 0; mi < 2; mi++)
        #pragma unroll
        for (int h = 0; h < 2; h++) {
            int rl = wm + mi * 16 + h * 8 + g;
            float sc = rs[rl];
            float* orow = out + ((size_t)b * S_ + i0 + rl) * D_ + wn * 32;
            #pragma unroll
            for (int nj = 0; nj < 4; nj++) {
                float2 w = { accpv[mi][nj][h * 2 + 0] * sc,
                             accpv[mi][nj][h * 2 + 1] * sc };
                *(float2*)(orow + nj * 8 + 2 * e) = w;
            }
        }

    // ---- pass 2: normalize attn stripe in place ----
    float* ab = attn + ((size_t)b * S_ + i0) * S_;
    #pragma unroll 4
    for (int idx = tid; idx < 64 * 512; idx += 128) {
        int row = idx >> 9, c4 = (idx & 511) << 2;
        float sc = rs[row];
        float4* p = (float4*)(ab + (size_t)row * S_ + c4);
        float4 t = *p;
        t.x *= sc; t.y *= sc; t.z *= sc; t.w *= sc;
        *p = t;
    }
}

// =============================================================================
extern "C" void kernel_launch(void* const* d_in, const int* in_sizes, int n_in,
                              void* d_out, int out_size) {
    const float* q = (const float*)d_in[0];
    const float* k = (const float*)d_in[1];
    const float* v = (const float*)d_in[2];
    const int* mask = (const int*)d_in[3];

    float* out  = (float*)d_out;                 // [B,S,D]
    float* attn = out + (size_t)B_ * S_ * D_;    // [B,S,S]

    const int SMEM = 52480;  // 51.25 KB -> 4 CTAs/SM
    cudaFuncSetAttribute(fused_attn_kernel,
                         cudaFuncAttributeMaxDynamicSharedMemorySize, SMEM);

    dim3 grid(S_ / 64, B_);
    fused_attn_kernel<<<grid, 128, SMEM>>>(q, k, v, mask, attn, out);
}